// round 8
// baseline (speedup 1.0000x reference)
#include <cuda_runtime.h>
#include <math.h>

#define BATCH 64
#define NPTS  512
#define DIM   512
#define NIDS  32                     // track ids are in [-1, 32)
#define CHUNKS 16                    // dist blocks per batch
#define DBLOCKS (BATCH * CHUNKS)     // 1024
#define DTHREADS 256
#define DWARPS (DTHREADS / 32)       // 8
#define APW (NPTS / CHUNKS / DWARPS) // 4 anchors per warp (2 interleaved pairs)
#define KSTEPS (DIM / 4 / 32)        // 4 float4 k-steps per row

__device__ __constant__ float c_margin = 0.3f;
__device__ __constant__ float c_eps    = 1e-6f;

// scratch (no allocations allowed) — zero-initialized; last block resets.
__device__ float        g_tot;
__device__ int          g_cntall;
__device__ unsigned int g_ticket;

// ---------------------------------------------------------------------------
// R8: R5-R7 established the kernel is load-latency bound (warm-state L2
// resident) and that registers-for-MLP beats occupancy. This round makes the
// trade explicit:
//   - double-buffered k-loop: 6 float4 loads for step k+1 issue before step
//     k's FMAs consume its 6 -> ~12 LDG.128 in flight per warp
//   - __ldcs on the once-streamed anchor rows so reused pos/neg rows stay
//     L1-resident
//   - everything else identical to R7 (tables, pair interleave, atomic finish)
//
// Closed-form replacement for argmax-of-mask (ids in [-1, 32)):
//   pos(i) = first[m] != i ? first[m] : second[m]     (needs count[m] >= 2)
//   neg(i) = ids[j1] != m ? j1 : j2                   (needs nvalid > count[m])
// ---------------------------------------------------------------------------
__global__ void dist_kernel(const float* __restrict__ feats,
                            const int*   __restrict__ ids,
                            float*       __restrict__ out,
                            int out_size)
{
    const int bk    = blockIdx.x;
    const int b     = bk / CHUNKS;
    const int chunk = bk % CHUNKS;
    const int wid   = threadIdx.x >> 5;
    const int lane  = threadIdx.x & 31;
    const int t     = threadIdx.x;

    __shared__ int s_first[NIDS];
    __shared__ int s_second[NIDS];
    __shared__ int s_count[NIDS];
    __shared__ int s_j1;      // first valid index overall
    __shared__ int s_j2;      // first valid index with id != ids[j1]
    __shared__ int s_idj1;    // ids[j1]
    __shared__ int s_nvalid;
    __shared__ float s_tot;
    __shared__ int   s_cnt;

    if (t < NIDS) {
        s_first[t]  = 0x7fffffff;
        s_second[t] = 0x7fffffff;
        s_count[t]  = 0;
    }
    if (t == 0) {
        s_j1 = 0x7fffffff;
        s_j2 = 0x7fffffff;
        s_nvalid = 0;
        s_tot = 0.0f;
        s_cnt = 0;
    }
    __syncthreads();

    // Pass 1: first occurrence per id, per-id counts, first valid overall.
    const int i0  = t;
    const int i1  = t + DTHREADS;
    const int id0 = ids[b * NPTS + i0];
    const int id1 = ids[b * NPTS + i1];
    if (id0 >= 0) {
        atomicMin(&s_first[id0], i0);
        atomicAdd(&s_count[id0], 1);
        atomicMin(&s_j1, i0);
    }
    if (id1 >= 0) {
        atomicMin(&s_first[id1], i1);
        atomicAdd(&s_count[id1], 1);
        atomicMin(&s_j1, i1);
    }
    int nv = __syncthreads_count(id0 >= 0);
    nv    += __syncthreads_count(id1 >= 0);
    if (t == 0) {
        s_nvalid = nv;
        s_idj1 = (s_j1 < NPTS) ? ids[b * NPTS + s_j1] : -2;
    }
    __syncthreads();

    // Pass 2: second occurrence per id; first valid with id != ids[j1].
    const int idj1 = s_idj1;
    if (id0 >= 0) {
        if (i0 != s_first[id0]) atomicMin(&s_second[id0], i0);
        if (id0 != idj1)        atomicMin(&s_j2, i0);
    }
    if (id1 >= 0) {
        if (i1 != s_first[id1]) atomicMin(&s_second[id1], i1);
        if (id1 != idj1)        atomicMin(&s_j2, i1);
    }
    __syncthreads();

    const int nvalid = s_nvalid;
    const int j1 = s_j1;
    const int j2 = s_j2;

    float w_tot = 0.0f;
    int   w_cnt = 0;

    const int a_base = chunk * (NPTS / CHUNKS) + wid * APW;
    const float eps = c_eps;
    const float* __restrict__ base = feats + (size_t)b * NPTS * DIM;

    #pragma unroll
    for (int pair = 0; pair < APW / 2; ++pair) {
        const int iA = a_base + pair * 2;
        const int iB = iA + 1;

        // Resolve (p, n, ok) for both anchors; invalid -> self-row, masked.
        const int mA = ids[b * NPTS + iA];
        const int mB = ids[b * NPTS + iB];
        const int cmA = (mA >= 0) ? s_count[mA] : 0;
        const int cmB = (mB >= 0) ? s_count[mB] : 0;
        const int okA = (mA >= 0) && (cmA >= 2) && (nvalid > cmA);
        const int okB = (mB >= 0) && (cmB >= 2) && (nvalid > cmB);

        int pA = iA, nA = iA, pB = iB, nB = iB;
        if (okA) {
            const int f = s_first[mA];
            pA = (f != iA) ? f : s_second[mA];
            nA = (idj1 != mA) ? j1 : j2;
        }
        if (okB) {
            const int f = s_first[mB];
            pB = (f != iB) ? f : s_second[mB];
            nB = (idj1 != mB) ? j1 : j2;
        }

        const float4* __restrict__ fiA = (const float4*)(base + (size_t)iA * DIM) + lane;
        const float4* __restrict__ fpA = (const float4*)(base + (size_t)pA * DIM) + lane;
        const float4* __restrict__ fnA = (const float4*)(base + (size_t)nA * DIM) + lane;
        const float4* __restrict__ fiB = (const float4*)(base + (size_t)iB * DIM) + lane;
        const float4* __restrict__ fpB = (const float4*)(base + (size_t)pB * DIM) + lane;
        const float4* __restrict__ fnB = (const float4*)(base + (size_t)nB * DIM) + lane;

        float sapA = 0.0f, sanA = 0.0f, sapB = 0.0f, sanB = 0.0f;

        // Double-buffered k-loop: issue k+1's 6 loads before consuming k's.
        float4 cA0, cP0, cN0, cB0, cQ0, cM0;   // current
        cA0 = __ldcs(fiA);        // anchor rows: streamed once, evict-first
        cP0 = fpA[0];
        cN0 = fnA[0];
        cB0 = __ldcs(fiB);
        cQ0 = fpB[0];
        cM0 = fnB[0];

        #pragma unroll
        for (int k = 0; k < KSTEPS; ++k) {
            float4 nA4v, nP4v, nN4v, nB4v, nQ4v, nM4v;
            if (k < KSTEPS - 1) {
                const int nk = (k + 1) * 32;
                nA4v = __ldcs(fiA + nk);
                nP4v = fpA[nk];
                nN4v = fnA[nk];
                nB4v = __ldcs(fiB + nk);
                nQ4v = fpB[nk];
                nM4v = fnB[nk];
            }
            float d;
            d = cA0.x - cP0.x + eps; sapA = fmaf(d, d, sapA);
            d = cA0.y - cP0.y + eps; sapA = fmaf(d, d, sapA);
            d = cA0.z - cP0.z + eps; sapA = fmaf(d, d, sapA);
            d = cA0.w - cP0.w + eps; sapA = fmaf(d, d, sapA);
            d = cA0.x - cN0.x + eps; sanA = fmaf(d, d, sanA);
            d = cA0.y - cN0.y + eps; sanA = fmaf(d, d, sanA);
            d = cA0.z - cN0.z + eps; sanA = fmaf(d, d, sanA);
            d = cA0.w - cN0.w + eps; sanA = fmaf(d, d, sanA);
            d = cB0.x - cQ0.x + eps; sapB = fmaf(d, d, sapB);
            d = cB0.y - cQ0.y + eps; sapB = fmaf(d, d, sapB);
            d = cB0.z - cQ0.z + eps; sapB = fmaf(d, d, sapB);
            d = cB0.w - cQ0.w + eps; sapB = fmaf(d, d, sapB);
            d = cB0.x - cM0.x + eps; sanB = fmaf(d, d, sanB);
            d = cB0.y - cM0.y + eps; sanB = fmaf(d, d, sanB);
            d = cB0.z - cM0.z + eps; sanB = fmaf(d, d, sanB);
            d = cB0.w - cM0.w + eps; sanB = fmaf(d, d, sanB);
            if (k < KSTEPS - 1) {
                cA0 = nA4v; cP0 = nP4v; cN0 = nN4v;
                cB0 = nB4v; cQ0 = nQ4v; cM0 = nM4v;
            }
        }

        // Four independent butterfly chains — pipelined by the scheduler.
        #pragma unroll
        for (int o = 16; o > 0; o >>= 1) {
            sapA += __shfl_xor_sync(0xFFFFFFFFu, sapA, o);
            sanA += __shfl_xor_sync(0xFFFFFFFFu, sanA, o);
            sapB += __shfl_xor_sync(0xFFFFFFFFu, sapB, o);
            sanB += __shfl_xor_sync(0xFFFFFFFFu, sanB, o);
        }
        if (lane == 0) {
            if (okA) {
                const float per = sqrtf(sapA) - sqrtf(sanA) + c_margin;
                if (per > 0.0f) w_tot += per;
                w_cnt++;
            }
            if (okB) {
                const float per = sqrtf(sapB) - sqrtf(sanB) + c_margin;
                if (per > 0.0f) w_tot += per;
                w_cnt++;
            }
        }
    }

    if (lane == 0) {
        atomicAdd(&s_tot, w_tot);
        atomicAdd(&s_cnt, w_cnt);
    }
    __syncthreads();

    if (t == 0) {
        atomicAdd(&g_tot, s_tot);
        atomicAdd(&g_cntall, s_cnt);
        __threadfence();
        const unsigned int old = atomicAdd(&g_ticket, 1u);
        if (old == DBLOCKS - 1) {
            __threadfence();                 // order: see all blocks' adds
            const float T = g_tot;
            const int   C = g_cntall;
            const float loss = (C > 0) ? (T / (float)C) : 0.0f;
            if (out_size > 0) out[0] = loss; // tracking_loss
            if (out_size > 1) out[1] = loss; // loss_triplet
            if (out_size > 2) out[2] = 0.0f; // loss_id
            g_tot    = 0.0f;                 // reset for next graph replay
            g_cntall = 0;
            g_ticket = 0;
            __threadfence();
        }
    }
}

extern "C" void kernel_launch(void* const* d_in, const int* in_sizes, int n_in,
                              void* d_out, int out_size)
{
    const float* feats = (const float*)d_in[0];
    const int*   ids   = (const int*)d_in[1];
    float*       out   = (float*)d_out;

    dist_kernel<<<DBLOCKS, DTHREADS>>>(feats, ids, out, out_size);
}